// round 9
// baseline (speedup 1.0000x reference)
#include <cuda_runtime.h>
#include <cstdint>

#define NN 100000
#define NE 1600000
#define BN_EPS 1e-5f
#define SCAN_BLK 1024
#define NSB ((NN + SCAN_BLK - 1) / SCAN_BLK)   // 98

// ---------------- scratch ----------------
__device__ __align__(16) float g_hs [(size_t)NN * 128];   // raw h (NO dinv)
__device__ __align__(16) float g_agg[(size_t)NN * 128];   // aggregated + bias (pre-BN)
__device__ float g_dinv[NN];
__device__ int   g_deg [NN];
__device__ int   g_off [NN + 1];
__device__ int   g_cur [NN];
__device__ int   g_src [NE];
__device__ int   g_dst [NE];
__device__ int   g_esrc [NE];      // CSR: sources grouped by dst
__device__ float g_enorm[NE];      // dinv[src]*dinv[dst], CSR order (streamed)
__device__ int   g_bsum[NSB];
__device__ int   g_is64;
__device__ float g_stats[512];     // sum/sumsq: L1 [0:256), L2 [256:512)
__device__ float g_sc[512];        // scale/shift: L1 [0:256), L2 [256:512)

// ---------------- init: zero deg + stats, detect edge dtype ----------------
__global__ void k_init0(const int* __restrict__ ei32) {
    int i = blockIdx.x * blockDim.x + threadIdx.x;
    if (i < NN)  g_deg[i] = 0;
    if (i < 512) g_stats[i] = 0.f;
    if (i == 0) {
        int is64 = 1;
        for (int j = 0; j < 64; j++)
            if (ei32[2 * j + 1] != 0) { is64 = 0; break; }
        g_is64 = is64;
    }
}

// ---------------- convert to int32 src/dst (clamped) + dst histogram ----------
__global__ void k_convert(const int* __restrict__ ei32) {
    int e = blockIdx.x * blockDim.x + threadIdx.x;
    if (e >= NE) return;
    int s, d;
    if (g_is64) {
        s = ei32[2 * (size_t)e];
        d = ei32[2 * ((size_t)NE + e)];
    } else {
        s = ei32[e];
        d = ei32[NE + e];
    }
    s = min(max(s, 0), NN - 1);
    d = min(max(d, 0), NN - 1);
    g_src[e] = s;
    g_dst[e] = d;
    atomicAdd(&g_deg[d], 1);
}

// ---------------- dinv = rsqrt(deg + 1) ----------------
__global__ void k_dinv() {
    int i = blockIdx.x * blockDim.x + threadIdx.x;
    if (i < NN) g_dinv[i] = rsqrtf((float)(g_deg[i] + 1));
}

// ---------------- scan stage 1: per-block sums ----------------
__global__ void k_bsum() {
    __shared__ int ws[8];
    int b = blockIdx.x, tid = threadIdx.x;
    int i = b * SCAN_BLK + tid * 4;
    int s = 0;
#pragma unroll
    for (int j = 0; j < 4; j++) { int idx = i + j; if (idx < NN) s += g_deg[idx]; }
#pragma unroll
    for (int o = 16; o; o >>= 1) s += __shfl_down_sync(~0u, s, o);
    if ((tid & 31) == 0) ws[tid >> 5] = s;
    __syncthreads();
    if (tid == 0) { int t = 0; for (int j = 0; j < 8; j++) t += ws[j]; g_bsum[b] = t; }
}

// ---------------- scan stage 2: exclusive scan of block sums ----------------
__global__ void k_scanb() {
    int run = 0;
    for (int i = 0; i < NSB; i++) { int t = g_bsum[i]; g_bsum[i] = run; run += t; }
    g_off[NN] = run;
}

// ---------------- scan stage 3: per-block exclusive scan -> offsets + cursor ----
__global__ void k_off() {
    __shared__ int wsum[8];
    int b = blockIdx.x, tid = threadIdx.x;
    int i0 = b * SCAN_BLK + tid * 4;
    int d0 = (i0 + 0 < NN) ? g_deg[i0 + 0] : 0;
    int d1 = (i0 + 1 < NN) ? g_deg[i0 + 1] : 0;
    int d2 = (i0 + 2 < NN) ? g_deg[i0 + 2] : 0;
    int d3 = (i0 + 3 < NN) ? g_deg[i0 + 3] : 0;
    int t = d0 + d1 + d2 + d3;
    int lane = tid & 31, w = tid >> 5;
    int v = t;
#pragma unroll
    for (int o = 1; o < 32; o <<= 1) { int u = __shfl_up_sync(~0u, v, o); if (lane >= o) v += u; }
    if (lane == 31) wsum[w] = v;
    __syncthreads();
    if (tid == 0) { int run = 0; for (int j = 0; j < 8; j++) { int x = wsum[j]; wsum[j] = run; run += x; } }
    __syncthreads();
    int excl = wsum[w] + (v - t) + g_bsum[b];
    int e0 = excl, e1 = e0 + d0, e2 = e1 + d1, e3 = e2 + d2;
    if (i0 + 0 < NN) { g_off[i0 + 0] = e0; g_cur[i0 + 0] = e0; }
    if (i0 + 1 < NN) { g_off[i0 + 1] = e1; g_cur[i0 + 1] = e1; }
    if (i0 + 2 < NN) { g_off[i0 + 2] = e2; g_cur[i0 + 2] = e2; }
    if (i0 + 3 < NN) { g_off[i0 + 3] = e3; g_cur[i0 + 3] = e3; }
}

// ---------------- bucket placement: src index + streamed norm ----------------
__global__ void k_place() {
    int e = blockIdx.x * blockDim.x + threadIdx.x;
    if (e >= NE) return;
    int s = g_src[e];
    int d = g_dst[e];
    int pos = atomicAdd(&g_cur[d], 1);
    g_esrc[pos]  = s;
    g_enorm[pos] = g_dinv[s] * g_dinv[d];
}

// =====================================================================
// FFMA SGEMM (measured 110.9us): hs = act(A) @ W  (raw, no dinv)
// 128x128 tile, 256 threads, 8x8/thread, BK=16, reg prefetch,
// __launch_bounds__(256,2) -> 128 regs, 2 blocks/SM.
// =====================================================================
template <bool NORM>
__global__ void __launch_bounds__(256, 2) k_gemm128(const float* __restrict__ Ain,
                                                    const float* __restrict__ W, int scOff) {
    const float* __restrict__ A = NORM ? g_agg : Ain;
    __shared__ float As[16][128];
    __shared__ float Bs[16][128];
    __shared__ float sc_s[128], sh_s[128];

    const int tid = threadIdx.x;
    if (NORM) {
        if (tid < 128) {
            sc_s[tid] = g_sc[scOff + tid];
            sh_s[tid] = g_sc[scOff + 128 + tid];
        }
        __syncthreads();
    }

    const int row0 = blockIdx.x * 128;
    const int tx = tid & 15;
    const int ty = tid >> 4;

    const int am0 = (tid * 2 + 0) >> 2, ak0 = ((tid * 2 + 0) & 3) * 4;
    const int am1 = (tid * 2 + 1) >> 2, ak1 = ((tid * 2 + 1) & 3) * 4;
    const int bk0 = (tid * 2 + 0) >> 5, bc0 = ((tid * 2 + 0) & 31) * 4;
    const int bk1 = (tid * 2 + 1) >> 5, bc1 = ((tid * 2 + 1) & 31) * 4;

    float4 ra0, ra1, rb0, rb1;

    auto loadA = [&](int kb, int m, int k, float4& out) {
        float4 v = make_float4(0.f, 0.f, 0.f, 0.f);
        int r = row0 + m;
        if (r < NN) v = *(const float4*)&A[(size_t)r * 128 + kb + k];
        if (NORM) {
            int c = kb + k;
            v.x = fmaxf(fmaf(v.x, sc_s[c + 0], sh_s[c + 0]), 0.f);
            v.y = fmaxf(fmaf(v.y, sc_s[c + 1], sh_s[c + 1]), 0.f);
            v.z = fmaxf(fmaf(v.z, sc_s[c + 2], sh_s[c + 2]), 0.f);
            v.w = fmaxf(fmaf(v.w, sc_s[c + 3], sh_s[c + 3]), 0.f);
        }
        out = v;
    };
    auto stage = [&]() {
        As[ak0 + 0][am0] = ra0.x; As[ak0 + 1][am0] = ra0.y;
        As[ak0 + 2][am0] = ra0.z; As[ak0 + 3][am0] = ra0.w;
        As[ak1 + 0][am1] = ra1.x; As[ak1 + 1][am1] = ra1.y;
        As[ak1 + 2][am1] = ra1.z; As[ak1 + 3][am1] = ra1.w;
        *(float4*)&Bs[bk0][bc0] = rb0;
        *(float4*)&Bs[bk1][bc1] = rb1;
    };

    loadA(0, am0, ak0, ra0);
    loadA(0, am1, ak1, ra1);
    rb0 = *(const float4*)&W[(size_t)bk0 * 128 + bc0];
    rb1 = *(const float4*)&W[(size_t)bk1 * 128 + bc1];
    stage();
    __syncthreads();

    float acc[8][8];
#pragma unroll
    for (int i = 0; i < 8; i++)
#pragma unroll
        for (int j = 0; j < 8; j++) acc[i][j] = 0.f;

#pragma unroll
    for (int kb = 0; kb < 128; kb += 16) {
        const bool more = (kb + 16) < 128;
        if (more) {
            loadA(kb + 16, am0, ak0, ra0);
            loadA(kb + 16, am1, ak1, ra1);
            rb0 = *(const float4*)&W[(size_t)(kb + 16 + bk0) * 128 + bc0];
            rb1 = *(const float4*)&W[(size_t)(kb + 16 + bk1) * 128 + bc1];
        }

#pragma unroll
        for (int k = 0; k < 16; k++) {
            float4 a0 = *(float4*)&As[k][ty * 8];
            float4 a1 = *(float4*)&As[k][ty * 8 + 4];
            float4 b0 = *(float4*)&Bs[k][tx * 8];
            float4 b1 = *(float4*)&Bs[k][tx * 8 + 4];
            float a[8] = {a0.x, a0.y, a0.z, a0.w, a1.x, a1.y, a1.z, a1.w};
            float bb[8] = {b0.x, b0.y, b0.z, b0.w, b1.x, b1.y, b1.z, b1.w};
#pragma unroll
            for (int i = 0; i < 8; i++)
#pragma unroll
                for (int j = 0; j < 8; j++) acc[i][j] = fmaf(a[i], bb[j], acc[i][j]);
        }

        if (more) {
            __syncthreads();
            stage();
            __syncthreads();
        }
    }

    // epilogue: raw h (norm applied in aggregate via streamed enorm)
#pragma unroll
    for (int i = 0; i < 8; i++) {
        int r = row0 + ty * 8 + i;
        if (r >= NN) break;
#pragma unroll
        for (int j = 0; j < 8; j += 4) {
            float4 v;
            v.x = acc[i][j + 0];
            v.y = acc[i][j + 1];
            v.z = acc[i][j + 2];
            v.w = acc[i][j + 3];
            *(float4*)&g_hs[(size_t)r * 128 + tx * 8 + j] = v;
        }
    }
}

// ---------------- SGEMM 128x64 tile (40 valid cols): layer 3, always NORM --------
__global__ void __launch_bounds__(256, 2) k_gemm40(const float* __restrict__ W, int scOff) {
    const float* __restrict__ A = g_agg;
    __shared__ float As[16][128];
    __shared__ float Bs[16][64];
    __shared__ float sc_s[128], sh_s[128];

    const int tid = threadIdx.x;
    if (tid < 128) {
        sc_s[tid] = g_sc[scOff + tid];
        sh_s[tid] = g_sc[scOff + 128 + tid];
    }
    __syncthreads();

    const int row0 = blockIdx.x * 128;
    const int tx = tid & 15;      // 16 x 4 cols = 64
    const int ty = tid >> 4;      // 16 x 8 rows = 128

    float acc[8][4];
#pragma unroll
    for (int i = 0; i < 8; i++)
#pragma unroll
        for (int j = 0; j < 4; j++) acc[i][j] = 0.f;

    for (int kb = 0; kb < 128; kb += 16) {
#pragma unroll
        for (int i = 0; i < 2; i++) {
            int f = tid * 2 + i;
            int m = f >> 2;
            int k4 = f & 3;
            int r = row0 + m;
            float4 v = make_float4(0.f, 0.f, 0.f, 0.f);
            if (r < NN) v = *(const float4*)&A[(size_t)r * 128 + kb + k4 * 4];
            int c = kb + k4 * 4;
            v.x = fmaxf(fmaf(v.x, sc_s[c + 0], sh_s[c + 0]), 0.f);
            v.y = fmaxf(fmaf(v.y, sc_s[c + 1], sh_s[c + 1]), 0.f);
            v.z = fmaxf(fmaf(v.z, sc_s[c + 2], sh_s[c + 2]), 0.f);
            v.w = fmaxf(fmaf(v.w, sc_s[c + 3], sh_s[c + 3]), 0.f);
            As[k4 * 4 + 0][m] = v.x;
            As[k4 * 4 + 1][m] = v.y;
            As[k4 * 4 + 2][m] = v.z;
            As[k4 * 4 + 3][m] = v.w;
        }
        {
            int k = tid >> 4;
            int c4 = tid & 15;
            float4 v = make_float4(0.f, 0.f, 0.f, 0.f);
            if (c4 * 4 < 40) v = *(const float4*)&W[(size_t)(kb + k) * 40 + c4 * 4];
            *(float4*)&Bs[k][c4 * 4] = v;
        }
        __syncthreads();

#pragma unroll
        for (int k = 0; k < 16; k++) {
            float4 a0 = *(float4*)&As[k][ty * 8];
            float4 a1 = *(float4*)&As[k][ty * 8 + 4];
            float4 bv = *(float4*)&Bs[k][tx * 4];
            float a[8] = {a0.x, a0.y, a0.z, a0.w, a1.x, a1.y, a1.z, a1.w};
#pragma unroll
            for (int i = 0; i < 8; i++) {
                acc[i][0] = fmaf(a[i], bv.x, acc[i][0]);
                acc[i][1] = fmaf(a[i], bv.y, acc[i][1]);
                acc[i][2] = fmaf(a[i], bv.z, acc[i][2]);
                acc[i][3] = fmaf(a[i], bv.w, acc[i][3]);
            }
        }
        __syncthreads();
    }

    if (tx < 10) {
#pragma unroll
        for (int i = 0; i < 8; i++) {
            int r = row0 + ty * 8 + i;
            if (r >= NN) break;
            float4 v;
            v.x = acc[i][0];
            v.y = acc[i][1];
            v.z = acc[i][2];
            v.w = acc[i][3];
            *(float4*)&g_hs[(size_t)r * 40 + tx * 4] = v;
        }
    }
}

// ---------------- CSR aggregate (C=128): streamed enorm + bias + BN stats ----
__global__ void __launch_bounds__(256) k_agg128(const float* __restrict__ bias, int statsOff) {
    __shared__ float sstat[256];
    int tid = threadIdx.x;
    sstat[tid] = 0.f;
    __syncthreads();

    int lane = tid & 31;
    int gw = (blockIdx.x * blockDim.x + tid) >> 5;
    int nw = (gridDim.x * blockDim.x) >> 5;
    float4 b = *(const float4*)&bias[lane * 4];
    float4 s1 = make_float4(0.f, 0.f, 0.f, 0.f);
    float4 s2 = make_float4(0.f, 0.f, 0.f, 0.f);

    for (int n = gw; n < NN; n += nw) {
        float dn = g_dinv[n];
        float w0 = dn * dn;                     // self-loop norm
        float4 h0 = *(const float4*)&g_hs[(size_t)n * 128 + lane * 4];
        float4 acc;
        acc.x = h0.x * w0; acc.y = h0.y * w0; acc.z = h0.z * w0; acc.w = h0.w * w0;
        int beg = g_off[n], end = g_off[n + 1];
        for (int i = beg; i < end; i++) {
            int s = g_esrc[i];                  // coalesced stream
            float w = g_enorm[i];               // coalesced stream
            float4 v = *(const float4*)&g_hs[(size_t)s * 128 + lane * 4];
            acc.x = fmaf(v.x, w, acc.x);
            acc.y = fmaf(v.y, w, acc.y);
            acc.z = fmaf(v.z, w, acc.z);
            acc.w = fmaf(v.w, w, acc.w);
        }
        float4 val;
        val.x = acc.x + b.x;
        val.y = acc.y + b.y;
        val.z = acc.z + b.z;
        val.w = acc.w + b.w;
        *(float4*)&g_agg[(size_t)n * 128 + lane * 4] = val;
        s1.x += val.x; s1.y += val.y; s1.z += val.z; s1.w += val.w;
        s2.x += val.x * val.x; s2.y += val.y * val.y;
        s2.z += val.z * val.z; s2.w += val.w * val.w;
    }

    atomicAdd(&sstat[lane * 4 + 0], s1.x);
    atomicAdd(&sstat[lane * 4 + 1], s1.y);
    atomicAdd(&sstat[lane * 4 + 2], s1.z);
    atomicAdd(&sstat[lane * 4 + 3], s1.w);
    atomicAdd(&sstat[128 + lane * 4 + 0], s2.x);
    atomicAdd(&sstat[128 + lane * 4 + 1], s2.y);
    atomicAdd(&sstat[128 + lane * 4 + 2], s2.z);
    atomicAdd(&sstat[128 + lane * 4 + 3], s2.w);
    __syncthreads();
    atomicAdd(&g_stats[statsOff + tid], sstat[tid]);
}

// ---------------- CSR aggregate (C=40): streamed enorm, direct output -----------
__global__ void __launch_bounds__(256) k_agg40(const float* __restrict__ b3,
                                               float* __restrict__ out) {
    int tid = threadIdx.x;
    int lane = tid & 31;
    int gw = (blockIdx.x * blockDim.x + tid) >> 5;
    int nw = (gridDim.x * blockDim.x) >> 5;
    bool act = lane < 10;
    float4 b = make_float4(0.f, 0.f, 0.f, 0.f);
    if (act) b = *(const float4*)&b3[lane * 4];

    for (int n = gw; n < NN; n += nw) {
        float dn = g_dinv[n];
        float w0 = dn * dn;
        int beg = g_off[n], end = g_off[n + 1];
        float4 acc = make_float4(0.f, 0.f, 0.f, 0.f);
        if (act) {
            float4 h0 = *(const float4*)&g_hs[(size_t)n * 40 + lane * 4];
            acc.x = h0.x * w0; acc.y = h0.y * w0; acc.z = h0.z * w0; acc.w = h0.w * w0;
        }
        for (int i = beg; i < end; i++) {
            int s = g_esrc[i];
            float w = g_enorm[i];
            if (act) {
                float4 v = *(const float4*)&g_hs[(size_t)s * 40 + lane * 4];
                acc.x = fmaf(v.x, w, acc.x);
                acc.y = fmaf(v.y, w, acc.y);
                acc.z = fmaf(v.z, w, acc.z);
                acc.w = fmaf(v.w, w, acc.w);
            }
        }
        if (act) {
            float4 o;
            o.x = acc.x + b.x;
            o.y = acc.y + b.y;
            o.z = acc.z + b.z;
            o.w = acc.w + b.w;
            *(float4*)&out[(size_t)n * 40 + lane * 4] = o;
        }
    }
}

// ---------------- finalize BN ----------------
__global__ void k_finalize(const float* __restrict__ gamma, const float* __restrict__ beta,
                           int statsOff, int scOff) {
    int c = threadIdx.x;            // 128 threads, 1 block
    float inv_n = 1.f / (float)NN;
    float mean = g_stats[statsOff + c] * inv_n;
    float var  = g_stats[statsOff + 128 + c] * inv_n - mean * mean;
    float inv  = rsqrtf(var + BN_EPS);
    float sc   = gamma[c] * inv;
    g_sc[scOff + c]       = sc;
    g_sc[scOff + 128 + c] = beta[c] - mean * sc;
}

// ---------------- launch: fork FULL edge pipeline under GEMM1 ----------------
extern "C" void kernel_launch(void* const* d_in, const int* in_sizes, int n_in,
                              void* d_out, int out_size) {
    const float* x    = (const float*)d_in[0];
    const int*   ei32 = (const int*)d_in[1];
    const float* W1 = (const float*)d_in[2];
    const float* b1 = (const float*)d_in[3];
    const float* g1 = (const float*)d_in[4];
    const float* t1 = (const float*)d_in[5];
    const float* W2 = (const float*)d_in[6];
    const float* b2 = (const float*)d_in[7];
    const float* g2 = (const float*)d_in[8];
    const float* t2 = (const float*)d_in[9];
    const float* W3 = (const float*)d_in[10];
    const float* b3 = (const float*)d_in[11];
    float* out = (float*)d_out;

    const int gemmBlocks = (NN + 127) / 128;     // 782
    const int aggBlocks  = 1184;
    const int edgeBlocks = (NE + 255) / 256;     // 6250

    static cudaStream_t s2 = nullptr;
    static cudaEvent_t evF = nullptr, evJ = nullptr;
    if (s2 == nullptr) {
        cudaStreamCreateWithFlags(&s2, cudaStreamNonBlocking);
        cudaEventCreateWithFlags(&evF, cudaEventDisableTiming);
        cudaEventCreateWithFlags(&evJ, cudaEventDisableTiming);
    }

    // fork s2 from the capture origin
    cudaEventRecord(evF, 0);
    cudaStreamWaitEvent(s2, evF, 0);

    // GEMM1 on main stream — fully independent of the edge pipeline now
    k_gemm128<false><<<gemmBlocks, 256>>>(x, W1, 0);

    // entire edge pipeline on s2, hidden under GEMM1 (~62us vs 111us)
    k_init0  <<<(NN + 255) / 256, 256, 0, s2>>>(ei32);
    k_convert<<<edgeBlocks, 256, 0, s2>>>(ei32);
    k_dinv   <<<(NN + 255) / 256, 256, 0, s2>>>();
    k_bsum   <<<NSB, 256, 0, s2>>>();
    k_scanb  <<<1, 1, 0, s2>>>();
    k_off    <<<NSB, 256, 0, s2>>>();
    k_place  <<<edgeBlocks, 256, 0, s2>>>();

    // join
    cudaEventRecord(evJ, s2);
    cudaStreamWaitEvent(0, evJ, 0);

    // layer 1 aggregate + BN
    k_agg128<<<aggBlocks, 256>>>(b1, 0);
    k_finalize<<<1, 128>>>(g1, t1, 0, 0);

    // layer 2 (BN+ReLU fused into A-load)
    k_gemm128<true><<<gemmBlocks, 256>>>(nullptr, W2, 0);
    k_agg128<<<aggBlocks, 256>>>(b2, 256);
    k_finalize<<<1, 128>>>(g2, t2, 256, 256);

    // layer 3 (output, 40 cols)
    k_gemm40<<<gemmBlocks, 256>>>(W3, 256);
    k_agg40<<<aggBlocks, 256>>>(b3, out);
}

// round 10
// speedup vs baseline: 1.1502x; 1.1502x over previous
#include <cuda_runtime.h>
#include <cstdint>

#define NN 100000
#define NE 1600000
#define BN_EPS 1e-5f
#define SCAN_BLK 1024
#define NSB ((NN + SCAN_BLK - 1) / SCAN_BLK)   // 98

// ---------------- scratch ----------------
__device__ __align__(16) float g_hs [(size_t)NN * 128];   // h * dinv[row]
__device__ __align__(16) float g_agg[(size_t)NN * 128];   // aggregated + bias (pre-BN)
__device__ float g_dinv[NN];
__device__ int   g_deg [NN];
__device__ int   g_off [NN + 1];
__device__ int   g_cur [NN];
__device__ int   g_src [NE];
__device__ int   g_dst [NE];
__device__ int   g_esrc[NE];       // CSR: sources grouped by dst
__device__ int   g_bsum[NSB];
__device__ int   g_is64;
__device__ float g_stats[512];     // sum/sumsq: L1 [0:256), L2 [256:512)
__device__ float g_sc[512];        // scale/shift: L1 [0:256), L2 [256:512)

// ---------------- init: zero deg + stats + detect edge dtype ----------------
__global__ void k_init0(const int* __restrict__ ei32) {
    int i = blockIdx.x * blockDim.x + threadIdx.x;
    if (i < NN)  g_deg[i] = 0;
    if (i < 512) g_stats[i] = 0.f;
    if (i == 0) {
        int is64 = 1;
        for (int j = 0; j < 64; j++)
            if (ei32[2 * j + 1] != 0) { is64 = 0; break; }
        g_is64 = is64;
    }
}

// ---------------- convert to int32 src/dst (clamped) + dst histogram ----------
__global__ void k_convert(const int* __restrict__ ei32) {
    int e = blockIdx.x * blockDim.x + threadIdx.x;
    if (e >= NE) return;
    int s, d;
    if (g_is64) {
        s = ei32[2 * (size_t)e];
        d = ei32[2 * ((size_t)NE + e)];
    } else {
        s = ei32[e];
        d = ei32[NE + e];
    }
    s = min(max(s, 0), NN - 1);
    d = min(max(d, 0), NN - 1);
    g_src[e] = s;
    g_dst[e] = d;
    atomicAdd(&g_deg[d], 1);
}

// ---------------- dinv = rsqrt(deg + 1) ----------------
__global__ void k_dinv() {
    int i = blockIdx.x * blockDim.x + threadIdx.x;
    if (i < NN) g_dinv[i] = rsqrtf((float)(g_deg[i] + 1));
}

// ---------------- scan stage 1: per-block sums ----------------
__global__ void k_bsum() {
    __shared__ int ws[8];
    int b = blockIdx.x, tid = threadIdx.x;
    int i = b * SCAN_BLK + tid * 4;
    int s = 0;
#pragma unroll
    for (int j = 0; j < 4; j++) { int idx = i + j; if (idx < NN) s += g_deg[idx]; }
#pragma unroll
    for (int o = 16; o; o >>= 1) s += __shfl_down_sync(~0u, s, o);
    if ((tid & 31) == 0) ws[tid >> 5] = s;
    __syncthreads();
    if (tid == 0) { int t = 0; for (int j = 0; j < 8; j++) t += ws[j]; g_bsum[b] = t; }
}

// ---------------- scan stage 2: exclusive scan of block sums ----------------
__global__ void k_scanb() {
    int run = 0;
    for (int i = 0; i < NSB; i++) { int t = g_bsum[i]; g_bsum[i] = run; run += t; }
    g_off[NN] = run;
}

// ---------------- scan stage 3: per-block exclusive scan -> offsets + cursor ----
__global__ void k_off() {
    __shared__ int wsum[8];
    int b = blockIdx.x, tid = threadIdx.x;
    int i0 = b * SCAN_BLK + tid * 4;
    int d0 = (i0 + 0 < NN) ? g_deg[i0 + 0] : 0;
    int d1 = (i0 + 1 < NN) ? g_deg[i0 + 1] : 0;
    int d2 = (i0 + 2 < NN) ? g_deg[i0 + 2] : 0;
    int d3 = (i0 + 3 < NN) ? g_deg[i0 + 3] : 0;
    int t = d0 + d1 + d2 + d3;
    int lane = tid & 31, w = tid >> 5;
    int v = t;
#pragma unroll
    for (int o = 1; o < 32; o <<= 1) { int u = __shfl_up_sync(~0u, v, o); if (lane >= o) v += u; }
    if (lane == 31) wsum[w] = v;
    __syncthreads();
    if (tid == 0) { int run = 0; for (int j = 0; j < 8; j++) { int x = wsum[j]; wsum[j] = run; run += x; } }
    __syncthreads();
    int excl = wsum[w] + (v - t) + g_bsum[b];
    int e0 = excl, e1 = e0 + d0, e2 = e1 + d1, e3 = e2 + d2;
    if (i0 + 0 < NN) { g_off[i0 + 0] = e0; g_cur[i0 + 0] = e0; }
    if (i0 + 1 < NN) { g_off[i0 + 1] = e1; g_cur[i0 + 1] = e1; }
    if (i0 + 2 < NN) { g_off[i0 + 2] = e2; g_cur[i0 + 2] = e2; }
    if (i0 + 3 < NN) { g_off[i0 + 3] = e3; g_cur[i0 + 3] = e3; }
}

// ---------------- bucket placement ----------------
__global__ void k_place() {
    int e = blockIdx.x * blockDim.x + threadIdx.x;
    if (e >= NE) return;
    int d = g_dst[e];
    int pos = atomicAdd(&g_cur[d], 1);
    g_esrc[pos] = g_src[e];
}

// ---------------- SGEMM (R3-exact): hs = act(A) @ W * dinv ----------
// 128x128 tile, 256 threads, 8x8/thread, BK=16, single buffer, 2 syncs.
template <bool NORM>
__global__ void __launch_bounds__(256) k_gemm128(const float* __restrict__ Ain,
                                                 const float* __restrict__ W, int scOff) {
    const float* __restrict__ A = NORM ? g_agg : Ain;
    __shared__ float As[16][128];
    __shared__ float Bs[16][128];
    __shared__ float sc_s[128], sh_s[128];

    const int tid = threadIdx.x;
    if (NORM && tid < 128) {
        sc_s[tid] = g_sc[scOff + tid];
        sh_s[tid] = g_sc[scOff + 128 + tid];
    }
    __syncthreads();

    const int row0 = blockIdx.x * 128;
    const int tx = tid & 15;
    const int ty = tid >> 4;

    float acc[8][8];
#pragma unroll
    for (int i = 0; i < 8; i++)
#pragma unroll
        for (int j = 0; j < 8; j++) acc[i][j] = 0.f;

    for (int kb = 0; kb < 128; kb += 16) {
#pragma unroll
        for (int i = 0; i < 2; i++) {
            int f = tid * 2 + i;         // 0..511
            int m = f >> 2;
            int k4 = f & 3;
            int r = row0 + m;
            float4 v = make_float4(0.f, 0.f, 0.f, 0.f);
            if (r < NN) v = *(const float4*)&A[(size_t)r * 128 + kb + k4 * 4];
            if (NORM) {
                int c = kb + k4 * 4;
                v.x = fmaxf(fmaf(v.x, sc_s[c + 0], sh_s[c + 0]), 0.f);
                v.y = fmaxf(fmaf(v.y, sc_s[c + 1], sh_s[c + 1]), 0.f);
                v.z = fmaxf(fmaf(v.z, sc_s[c + 2], sh_s[c + 2]), 0.f);
                v.w = fmaxf(fmaf(v.w, sc_s[c + 3], sh_s[c + 3]), 0.f);
            }
            As[k4 * 4 + 0][m] = v.x;
            As[k4 * 4 + 1][m] = v.y;
            As[k4 * 4 + 2][m] = v.z;
            As[k4 * 4 + 3][m] = v.w;
        }
#pragma unroll
        for (int i = 0; i < 2; i++) {
            int f = tid * 2 + i;
            int k = f >> 5;
            int c4 = f & 31;
            *(float4*)&Bs[k][c4 * 4] = *(const float4*)&W[(size_t)(kb + k) * 128 + c4 * 4];
        }
        __syncthreads();

#pragma unroll
        for (int k = 0; k < 16; k++) {
            float4 a0 = *(float4*)&As[k][ty * 8];
            float4 a1 = *(float4*)&As[k][ty * 8 + 4];
            float4 b0 = *(float4*)&Bs[k][tx * 8];
            float4 b1 = *(float4*)&Bs[k][tx * 8 + 4];
            float a[8] = {a0.x, a0.y, a0.z, a0.w, a1.x, a1.y, a1.z, a1.w};
            float bb[8] = {b0.x, b0.y, b0.z, b0.w, b1.x, b1.y, b1.z, b1.w};
#pragma unroll
            for (int i = 0; i < 8; i++)
#pragma unroll
                for (int j = 0; j < 8; j++) acc[i][j] = fmaf(a[i], bb[j], acc[i][j]);
        }
        __syncthreads();
    }

#pragma unroll
    for (int i = 0; i < 8; i++) {
        int r = row0 + ty * 8 + i;
        if (r >= NN) break;
        float d = g_dinv[r];
#pragma unroll
        for (int j = 0; j < 8; j += 4) {
            float4 v;
            v.x = acc[i][j + 0] * d;
            v.y = acc[i][j + 1] * d;
            v.z = acc[i][j + 2] * d;
            v.w = acc[i][j + 3] * d;
            *(float4*)&g_hs[(size_t)r * 128 + tx * 8 + j] = v;
        }
    }
}

// ---------------- SGEMM 128x64 tile (40 valid cols): layer 3 (R3-exact) ----------
__global__ void __launch_bounds__(256) k_gemm40(const float* __restrict__ W, int scOff) {
    const float* __restrict__ A = g_agg;
    __shared__ float As[16][128];
    __shared__ float Bs[16][64];
    __shared__ float sc_s[128], sh_s[128];

    const int tid = threadIdx.x;
    if (tid < 128) {
        sc_s[tid] = g_sc[scOff + tid];
        sh_s[tid] = g_sc[scOff + 128 + tid];
    }
    __syncthreads();

    const int row0 = blockIdx.x * 128;
    const int tx = tid & 15;      // 16 x 4 cols = 64
    const int ty = tid >> 4;      // 16 x 8 rows = 128

    float acc[8][4];
#pragma unroll
    for (int i = 0; i < 8; i++)
#pragma unroll
        for (int j = 0; j < 4; j++) acc[i][j] = 0.f;

    for (int kb = 0; kb < 128; kb += 16) {
#pragma unroll
        for (int i = 0; i < 2; i++) {
            int f = tid * 2 + i;
            int m = f >> 2;
            int k4 = f & 3;
            int r = row0 + m;
            float4 v = make_float4(0.f, 0.f, 0.f, 0.f);
            if (r < NN) v = *(const float4*)&A[(size_t)r * 128 + kb + k4 * 4];
            int c = kb + k4 * 4;
            v.x = fmaxf(fmaf(v.x, sc_s[c + 0], sh_s[c + 0]), 0.f);
            v.y = fmaxf(fmaf(v.y, sc_s[c + 1], sh_s[c + 1]), 0.f);
            v.z = fmaxf(fmaf(v.z, sc_s[c + 2], sh_s[c + 2]), 0.f);
            v.w = fmaxf(fmaf(v.w, sc_s[c + 3], sh_s[c + 3]), 0.f);
            As[k4 * 4 + 0][m] = v.x;
            As[k4 * 4 + 1][m] = v.y;
            As[k4 * 4 + 2][m] = v.z;
            As[k4 * 4 + 3][m] = v.w;
        }
        {
            int k = tid >> 4;
            int c4 = tid & 15;
            float4 v = make_float4(0.f, 0.f, 0.f, 0.f);
            if (c4 * 4 < 40) v = *(const float4*)&W[(size_t)(kb + k) * 40 + c4 * 4];
            *(float4*)&Bs[k][c4 * 4] = v;
        }
        __syncthreads();

#pragma unroll
        for (int k = 0; k < 16; k++) {
            float4 a0 = *(float4*)&As[k][ty * 8];
            float4 a1 = *(float4*)&As[k][ty * 8 + 4];
            float4 bv = *(float4*)&Bs[k][tx * 4];
            float a[8] = {a0.x, a0.y, a0.z, a0.w, a1.x, a1.y, a1.z, a1.w};
#pragma unroll
            for (int i = 0; i < 8; i++) {
                acc[i][0] = fmaf(a[i], bv.x, acc[i][0]);
                acc[i][1] = fmaf(a[i], bv.y, acc[i][1]);
                acc[i][2] = fmaf(a[i], bv.z, acc[i][2]);
                acc[i][3] = fmaf(a[i], bv.w, acc[i][3]);
            }
        }
        __syncthreads();
    }

    if (tx < 10) {
#pragma unroll
        for (int i = 0; i < 8; i++) {
            int r = row0 + ty * 8 + i;
            if (r >= NN) break;
            float d = g_dinv[r];
            float4 v;
            v.x = acc[i][0] * d;
            v.y = acc[i][1] * d;
            v.z = acc[i][2] * d;
            v.w = acc[i][3] * d;
            *(float4*)&g_hs[(size_t)r * 40 + tx * 4] = v;
        }
    }
}

// ---------------- CSR aggregate (C=128): warp per node + bias + BN stats ----
__global__ void __launch_bounds__(256) k_agg128(const float* __restrict__ bias, int statsOff) {
    __shared__ float sstat[256];
    int tid = threadIdx.x;
    sstat[tid] = 0.f;
    __syncthreads();

    int lane = tid & 31;
    int gw = (blockIdx.x * blockDim.x + tid) >> 5;
    int nw = (gridDim.x * blockDim.x) >> 5;
    float4 b = *(const float4*)&bias[lane * 4];
    float4 s1 = make_float4(0.f, 0.f, 0.f, 0.f);
    float4 s2 = make_float4(0.f, 0.f, 0.f, 0.f);

    for (int n = gw; n < NN; n += nw) {
        float4 acc = *(const float4*)&g_hs[(size_t)n * 128 + lane * 4];  // self loop
        int beg = g_off[n], end = g_off[n + 1];
        for (int i = beg; i < end; i++) {
            int s = g_esrc[i];
            float4 v = *(const float4*)&g_hs[(size_t)s * 128 + lane * 4];
            acc.x += v.x; acc.y += v.y; acc.z += v.z; acc.w += v.w;
        }
        float d = g_dinv[n];
        float4 val;
        val.x = fmaf(acc.x, d, b.x);
        val.y = fmaf(acc.y, d, b.y);
        val.z = fmaf(acc.z, d, b.z);
        val.w = fmaf(acc.w, d, b.w);
        *(float4*)&g_agg[(size_t)n * 128 + lane * 4] = val;
        s1.x += val.x; s1.y += val.y; s1.z += val.z; s1.w += val.w;
        s2.x += val.x * val.x; s2.y += val.y * val.y;
        s2.z += val.z * val.z; s2.w += val.w * val.w;
    }

    atomicAdd(&sstat[lane * 4 + 0], s1.x);
    atomicAdd(&sstat[lane * 4 + 1], s1.y);
    atomicAdd(&sstat[lane * 4 + 2], s1.z);
    atomicAdd(&sstat[lane * 4 + 3], s1.w);
    atomicAdd(&sstat[128 + lane * 4 + 0], s2.x);
    atomicAdd(&sstat[128 + lane * 4 + 1], s2.y);
    atomicAdd(&sstat[128 + lane * 4 + 2], s2.z);
    atomicAdd(&sstat[128 + lane * 4 + 3], s2.w);
    __syncthreads();
    atomicAdd(&g_stats[statsOff + tid], sstat[tid]);
}

// ---------------- CSR aggregate (C=40): direct output write ----------------------
__global__ void __launch_bounds__(256) k_agg40(const float* __restrict__ b3,
                                               float* __restrict__ out) {
    int tid = threadIdx.x;
    int lane = tid & 31;
    int gw = (blockIdx.x * blockDim.x + tid) >> 5;
    int nw = (gridDim.x * blockDim.x) >> 5;
    bool act = lane < 10;
    float4 b = make_float4(0.f, 0.f, 0.f, 0.f);
    if (act) b = *(const float4*)&b3[lane * 4];

    for (int n = gw; n < NN; n += nw) {
        int beg = g_off[n], end = g_off[n + 1];
        float4 acc = make_float4(0.f, 0.f, 0.f, 0.f);
        if (act) acc = *(const float4*)&g_hs[(size_t)n * 40 + lane * 4];
        for (int i = beg; i < end; i++) {
            int s = g_esrc[i];
            if (act) {
                float4 v = *(const float4*)&g_hs[(size_t)s * 40 + lane * 4];
                acc.x += v.x; acc.y += v.y; acc.z += v.z; acc.w += v.w;
            }
        }
        if (act) {
            float d = g_dinv[n];
            float4 o;
            o.x = fmaf(acc.x, d, b.x);
            o.y = fmaf(acc.y, d, b.y);
            o.z = fmaf(acc.z, d, b.z);
            o.w = fmaf(acc.w, d, b.w);
            *(float4*)&out[(size_t)n * 40 + lane * 4] = o;
        }
    }
}

// ---------------- finalize BN ----------------
__global__ void k_finalize(const float* __restrict__ gamma, const float* __restrict__ beta,
                           int statsOff, int scOff) {
    int c = threadIdx.x;            // 128 threads, 1 block
    float inv_n = 1.f / (float)NN;
    float mean = g_stats[statsOff + c] * inv_n;
    float var  = g_stats[statsOff + 128 + c] * inv_n - mean * mean;
    float inv  = rsqrtf(var + BN_EPS);
    float sc   = gamma[c] * inv;
    g_sc[scOff + c]       = sc;
    g_sc[scOff + 128 + c] = beta[c] - mean * sc;
}

// ---------------- launch: R3 pipeline + CSR-build forked under GEMM1 -------------
extern "C" void kernel_launch(void* const* d_in, const int* in_sizes, int n_in,
                              void* d_out, int out_size) {
    const float* x    = (const float*)d_in[0];
    const int*   ei32 = (const int*)d_in[1];
    const float* W1 = (const float*)d_in[2];
    const float* b1 = (const float*)d_in[3];
    const float* g1 = (const float*)d_in[4];
    const float* t1 = (const float*)d_in[5];
    const float* W2 = (const float*)d_in[6];
    const float* b2 = (const float*)d_in[7];
    const float* g2 = (const float*)d_in[8];
    const float* t2 = (const float*)d_in[9];
    const float* W3 = (const float*)d_in[10];
    const float* b3 = (const float*)d_in[11];
    float* out = (float*)d_out;

    const int gemmBlocks = (NN + 127) / 128;     // 782
    const int aggBlocks  = 1184;
    const int edgeBlocks = (NE + 255) / 256;     // 6250

    static cudaStream_t s2 = nullptr;
    static cudaEvent_t evF = nullptr, evJ = nullptr;
    if (s2 == nullptr) {
        cudaStreamCreateWithFlags(&s2, cudaStreamNonBlocking);
        cudaEventCreateWithFlags(&evF, cudaEventDisableTiming);
        cudaEventCreateWithFlags(&evJ, cudaEventDisableTiming);
    }

    // preprocessing needed by GEMM1 epilogue (dinv) — on main stream
    k_init0  <<<(NN + 255) / 256, 256>>>(ei32);      // launch 1
    k_convert<<<edgeBlocks, 256>>>(ei32);            // launch 2
    k_dinv   <<<(NN + 255) / 256, 256>>>();          // launch 3

    // fork: CSR build on s2 (needs only g_deg/g_src/g_dst), GEMM1 on main
    cudaEventRecord(evF, 0);
    cudaStreamWaitEvent(s2, evF, 0);

    k_gemm128<false><<<gemmBlocks, 256>>>(x, W1, 0); // launch 4 (profiled slot)

    k_bsum <<<NSB, 256, 0, s2>>>();
    k_scanb<<<1, 1, 0, s2>>>();
    k_off  <<<NSB, 256, 0, s2>>>();
    k_place<<<edgeBlocks, 256, 0, s2>>>();

    // join before aggregate
    cudaEventRecord(evJ, s2);
    cudaStreamWaitEvent(0, evJ, 0);

    // layer 1 aggregate + BN
    k_agg128<<<aggBlocks, 256>>>(b1, 0);
    k_finalize<<<1, 128>>>(g1, t1, 0, 0);

    // layer 2 (BN+ReLU fused into A-load)
    k_gemm128<true><<<gemmBlocks, 256>>>(nullptr, W2, 0);
    k_agg128<<<aggBlocks, 256>>>(b2, 256);
    k_finalize<<<1, 128>>>(g2, t2, 256, 256);

    // layer 3 (output, 40 cols)
    k_gemm40<<<gemmBlocks, 256>>>(W3, 256);
    k_agg40<<<aggBlocks, 256>>>(b3, out);
}

// round 11
// speedup vs baseline: 1.3373x; 1.1626x over previous
#include <cuda_runtime.h>
#include <cuda_fp16.h>
#include <cstdint>

#define NN 100000
#define NE 1600000
#define BN_EPS 1e-5f
#define SCAN_BLK 1024
#define NSB ((NN + SCAN_BLK - 1) / SCAN_BLK)   // 98

// ---------------- scratch ----------------
__device__ __align__(16) __half g_hs [(size_t)NN * 128];  // h * dinv[row], fp16
__device__ __align__(16) float  g_agg[(size_t)NN * 128];  // aggregated + bias (fp32)
__device__ float g_dinv[NN];
__device__ int   g_deg [NN];
__device__ int   g_off [NN + 1];
__device__ int   g_cur [NN];
__device__ int   g_src [NE];
__device__ int   g_dst [NE];
__device__ int   g_esrc[NE];       // CSR: sources grouped by dst
__device__ int   g_bsum[NSB];
__device__ int   g_is64;
__device__ float g_stats[512];     // sum/sumsq: L1 [0:256), L2 [256:512)
__device__ float g_sc[512];        // scale/shift: L1 [0:256), L2 [256:512)

__device__ __forceinline__ uint32_t f22h2(float a, float b) {
    __half2 h = __floats2half2_rn(a, b);
    return *reinterpret_cast<uint32_t*>(&h);
}

// ---------------- init: zero deg + stats + detect edge dtype ----------------
__global__ void k_init0(const int* __restrict__ ei32) {
    int i = blockIdx.x * blockDim.x + threadIdx.x;
    if (i < NN)  g_deg[i] = 0;
    if (i < 512) g_stats[i] = 0.f;
    if (i == 0) {
        int is64 = 1;
        for (int j = 0; j < 64; j++)
            if (ei32[2 * j + 1] != 0) { is64 = 0; break; }
        g_is64 = is64;
    }
}

// ---------------- convert to int32 src/dst (clamped) + dst histogram ----------
__global__ void k_convert(const int* __restrict__ ei32) {
    int e = blockIdx.x * blockDim.x + threadIdx.x;
    if (e >= NE) return;
    int s, d;
    if (g_is64) {
        s = ei32[2 * (size_t)e];
        d = ei32[2 * ((size_t)NE + e)];
    } else {
        s = ei32[e];
        d = ei32[NE + e];
    }
    s = min(max(s, 0), NN - 1);
    d = min(max(d, 0), NN - 1);
    g_src[e] = s;
    g_dst[e] = d;
    atomicAdd(&g_deg[d], 1);
}

// ---------------- dinv = rsqrt(deg + 1) ----------------
__global__ void k_dinv() {
    int i = blockIdx.x * blockDim.x + threadIdx.x;
    if (i < NN) g_dinv[i] = rsqrtf((float)(g_deg[i] + 1));
}

// ---------------- scan stage 1: per-block sums ----------------
__global__ void k_bsum() {
    __shared__ int ws[8];
    int b = blockIdx.x, tid = threadIdx.x;
    int i = b * SCAN_BLK + tid * 4;
    int s = 0;
#pragma unroll
    for (int j = 0; j < 4; j++) { int idx = i + j; if (idx < NN) s += g_deg[idx]; }
#pragma unroll
    for (int o = 16; o; o >>= 1) s += __shfl_down_sync(~0u, s, o);
    if ((tid & 31) == 0) ws[tid >> 5] = s;
    __syncthreads();
    if (tid == 0) { int t = 0; for (int j = 0; j < 8; j++) t += ws[j]; g_bsum[b] = t; }
}

// ---------------- scan stage 2: exclusive scan of block sums ----------------
__global__ void k_scanb() {
    int run = 0;
    for (int i = 0; i < NSB; i++) { int t = g_bsum[i]; g_bsum[i] = run; run += t; }
    g_off[NN] = run;
}

// ---------------- scan stage 3: per-block exclusive scan -> offsets + cursor ----
__global__ void k_off() {
    __shared__ int wsum[8];
    int b = blockIdx.x, tid = threadIdx.x;
    int i0 = b * SCAN_BLK + tid * 4;
    int d0 = (i0 + 0 < NN) ? g_deg[i0 + 0] : 0;
    int d1 = (i0 + 1 < NN) ? g_deg[i0 + 1] : 0;
    int d2 = (i0 + 2 < NN) ? g_deg[i0 + 2] : 0;
    int d3 = (i0 + 3 < NN) ? g_deg[i0 + 3] : 0;
    int t = d0 + d1 + d2 + d3;
    int lane = tid & 31, w = tid >> 5;
    int v = t;
#pragma unroll
    for (int o = 1; o < 32; o <<= 1) { int u = __shfl_up_sync(~0u, v, o); if (lane >= o) v += u; }
    if (lane == 31) wsum[w] = v;
    __syncthreads();
    if (tid == 0) { int run = 0; for (int j = 0; j < 8; j++) { int x = wsum[j]; wsum[j] = run; run += x; } }
    __syncthreads();
    int excl = wsum[w] + (v - t) + g_bsum[b];
    int e0 = excl, e1 = e0 + d0, e2 = e1 + d1, e3 = e2 + d2;
    if (i0 + 0 < NN) { g_off[i0 + 0] = e0; g_cur[i0 + 0] = e0; }
    if (i0 + 1 < NN) { g_off[i0 + 1] = e1; g_cur[i0 + 1] = e1; }
    if (i0 + 2 < NN) { g_off[i0 + 2] = e2; g_cur[i0 + 2] = e2; }
    if (i0 + 3 < NN) { g_off[i0 + 3] = e3; g_cur[i0 + 3] = e3; }
}

// ---------------- bucket placement ----------------
__global__ void k_place() {
    int e = blockIdx.x * blockDim.x + threadIdx.x;
    if (e >= NE) return;
    int d = g_dst[e];
    int pos = atomicAdd(&g_cur[d], 1);
    g_esrc[pos] = g_src[e];
}

// ---------------- SGEMM (R3-exact loop): hs(fp16) = act(A) @ W * dinv ----------
template <bool NORM>
__global__ void __launch_bounds__(256) k_gemm128(const float* __restrict__ Ain,
                                                 const float* __restrict__ W, int scOff) {
    const float* __restrict__ A = NORM ? g_agg : Ain;
    __shared__ float As[16][128];
    __shared__ float Bs[16][128];
    __shared__ float sc_s[128], sh_s[128];

    const int tid = threadIdx.x;
    if (NORM && tid < 128) {
        sc_s[tid] = g_sc[scOff + tid];
        sh_s[tid] = g_sc[scOff + 128 + tid];
    }
    __syncthreads();

    const int row0 = blockIdx.x * 128;
    const int tx = tid & 15;
    const int ty = tid >> 4;

    float acc[8][8];
#pragma unroll
    for (int i = 0; i < 8; i++)
#pragma unroll
        for (int j = 0; j < 8; j++) acc[i][j] = 0.f;

    for (int kb = 0; kb < 128; kb += 16) {
#pragma unroll
        for (int i = 0; i < 2; i++) {
            int f = tid * 2 + i;         // 0..511
            int m = f >> 2;
            int k4 = f & 3;
            int r = row0 + m;
            float4 v = make_float4(0.f, 0.f, 0.f, 0.f);
            if (r < NN) v = *(const float4*)&A[(size_t)r * 128 + kb + k4 * 4];
            if (NORM) {
                int c = kb + k4 * 4;
                v.x = fmaxf(fmaf(v.x, sc_s[c + 0], sh_s[c + 0]), 0.f);
                v.y = fmaxf(fmaf(v.y, sc_s[c + 1], sh_s[c + 1]), 0.f);
                v.z = fmaxf(fmaf(v.z, sc_s[c + 2], sh_s[c + 2]), 0.f);
                v.w = fmaxf(fmaf(v.w, sc_s[c + 3], sh_s[c + 3]), 0.f);
            }
            As[k4 * 4 + 0][m] = v.x;
            As[k4 * 4 + 1][m] = v.y;
            As[k4 * 4 + 2][m] = v.z;
            As[k4 * 4 + 3][m] = v.w;
        }
#pragma unroll
        for (int i = 0; i < 2; i++) {
            int f = tid * 2 + i;
            int k = f >> 5;
            int c4 = f & 31;
            *(float4*)&Bs[k][c4 * 4] = *(const float4*)&W[(size_t)(kb + k) * 128 + c4 * 4];
        }
        __syncthreads();

#pragma unroll
        for (int k = 0; k < 16; k++) {
            float4 a0 = *(float4*)&As[k][ty * 8];
            float4 a1 = *(float4*)&As[k][ty * 8 + 4];
            float4 b0 = *(float4*)&Bs[k][tx * 8];
            float4 b1 = *(float4*)&Bs[k][tx * 8 + 4];
            float a[8] = {a0.x, a0.y, a0.z, a0.w, a1.x, a1.y, a1.z, a1.w};
            float bb[8] = {b0.x, b0.y, b0.z, b0.w, b1.x, b1.y, b1.z, b1.w};
#pragma unroll
            for (int i = 0; i < 8; i++)
#pragma unroll
                for (int j = 0; j < 8; j++) acc[i][j] = fmaf(a[i], bb[j], acc[i][j]);
        }
        __syncthreads();
    }

    // epilogue: hs = half(acc * dinv[row])
#pragma unroll
    for (int i = 0; i < 8; i++) {
        int r = row0 + ty * 8 + i;
        if (r >= NN) break;
        float d = g_dinv[r];
#pragma unroll
        for (int j = 0; j < 8; j += 4) {
            uint2 u;
            u.x = f22h2(acc[i][j + 0] * d, acc[i][j + 1] * d);
            u.y = f22h2(acc[i][j + 2] * d, acc[i][j + 3] * d);
            *(uint2*)&g_hs[(size_t)r * 128 + tx * 8 + j] = u;
        }
    }
}

// ---------------- SGEMM 128x64 tile (40 valid cols): layer 3 --------------------
__global__ void __launch_bounds__(256) k_gemm40(const float* __restrict__ W, int scOff) {
    const float* __restrict__ A = g_agg;
    __shared__ float As[16][128];
    __shared__ float Bs[16][64];
    __shared__ float sc_s[128], sh_s[128];

    const int tid = threadIdx.x;
    if (tid < 128) {
        sc_s[tid] = g_sc[scOff + tid];
        sh_s[tid] = g_sc[scOff + 128 + tid];
    }
    __syncthreads();

    const int row0 = blockIdx.x * 128;
    const int tx = tid & 15;      // 16 x 4 cols = 64
    const int ty = tid >> 4;      // 16 x 8 rows = 128

    float acc[8][4];
#pragma unroll
    for (int i = 0; i < 8; i++)
#pragma unroll
        for (int j = 0; j < 4; j++) acc[i][j] = 0.f;

    for (int kb = 0; kb < 128; kb += 16) {
#pragma unroll
        for (int i = 0; i < 2; i++) {
            int f = tid * 2 + i;
            int m = f >> 2;
            int k4 = f & 3;
            int r = row0 + m;
            float4 v = make_float4(0.f, 0.f, 0.f, 0.f);
            if (r < NN) v = *(const float4*)&A[(size_t)r * 128 + kb + k4 * 4];
            int c = kb + k4 * 4;
            v.x = fmaxf(fmaf(v.x, sc_s[c + 0], sh_s[c + 0]), 0.f);
            v.y = fmaxf(fmaf(v.y, sc_s[c + 1], sh_s[c + 1]), 0.f);
            v.z = fmaxf(fmaf(v.z, sc_s[c + 2], sh_s[c + 2]), 0.f);
            v.w = fmaxf(fmaf(v.w, sc_s[c + 3], sh_s[c + 3]), 0.f);
            As[k4 * 4 + 0][m] = v.x;
            As[k4 * 4 + 1][m] = v.y;
            As[k4 * 4 + 2][m] = v.z;
            As[k4 * 4 + 3][m] = v.w;
        }
        {
            int k = tid >> 4;
            int c4 = tid & 15;
            float4 v = make_float4(0.f, 0.f, 0.f, 0.f);
            if (c4 * 4 < 40) v = *(const float4*)&W[(size_t)(kb + k) * 40 + c4 * 4];
            *(float4*)&Bs[k][c4 * 4] = v;
        }
        __syncthreads();

#pragma unroll
        for (int k = 0; k < 16; k++) {
            float4 a0 = *(float4*)&As[k][ty * 8];
            float4 a1 = *(float4*)&As[k][ty * 8 + 4];
            float4 bv = *(float4*)&Bs[k][tx * 4];
            float a[8] = {a0.x, a0.y, a0.z, a0.w, a1.x, a1.y, a1.z, a1.w};
#pragma unroll
            for (int i = 0; i < 8; i++) {
                acc[i][0] = fmaf(a[i], bv.x, acc[i][0]);
                acc[i][1] = fmaf(a[i], bv.y, acc[i][1]);
                acc[i][2] = fmaf(a[i], bv.z, acc[i][2]);
                acc[i][3] = fmaf(a[i], bv.w, acc[i][3]);
            }
        }
        __syncthreads();
    }

    if (tx < 10) {
#pragma unroll
        for (int i = 0; i < 8; i++) {
            int r = row0 + ty * 8 + i;
            if (r >= NN) break;
            float d = g_dinv[r];
            uint2 u;
            u.x = f22h2(acc[i][0] * d, acc[i][1] * d);
            u.y = f22h2(acc[i][2] * d, acc[i][3] * d);
            *(uint2*)&g_hs[(size_t)r * 40 + tx * 4] = u;
        }
    }
}

// ---------------- CSR aggregate (C=128): fp16 gather, fp32 accumulate ----------
__global__ void __launch_bounds__(256) k_agg128(const float* __restrict__ bias, int statsOff) {
    __shared__ float sstat[256];
    int tid = threadIdx.x;
    sstat[tid] = 0.f;
    __syncthreads();

    int lane = tid & 31;
    int gw = (blockIdx.x * blockDim.x + tid) >> 5;
    int nw = (gridDim.x * blockDim.x) >> 5;
    float4 b = *(const float4*)&bias[lane * 4];
    float4 s1 = make_float4(0.f, 0.f, 0.f, 0.f);
    float4 s2 = make_float4(0.f, 0.f, 0.f, 0.f);

    for (int n = gw; n < NN; n += nw) {
        float4 acc;
        {
            uint2 u = *(const uint2*)&g_hs[(size_t)n * 128 + lane * 4];  // self loop
            float2 f0 = __half22float2(*reinterpret_cast<__half2*>(&u.x));
            float2 f1 = __half22float2(*reinterpret_cast<__half2*>(&u.y));
            acc.x = f0.x; acc.y = f0.y; acc.z = f1.x; acc.w = f1.y;
        }
        int beg = g_off[n], end = g_off[n + 1];
        for (int i = beg; i < end; i++) {
            int s = g_esrc[i];
            uint2 u = *(const uint2*)&g_hs[(size_t)s * 128 + lane * 4];
            float2 f0 = __half22float2(*reinterpret_cast<__half2*>(&u.x));
            float2 f1 = __half22float2(*reinterpret_cast<__half2*>(&u.y));
            acc.x += f0.x; acc.y += f0.y; acc.z += f1.x; acc.w += f1.y;
        }
        float d = g_dinv[n];
        float4 val;
        val.x = fmaf(acc.x, d, b.x);
        val.y = fmaf(acc.y, d, b.y);
        val.z = fmaf(acc.z, d, b.z);
        val.w = fmaf(acc.w, d, b.w);
        *(float4*)&g_agg[(size_t)n * 128 + lane * 4] = val;
        s1.x += val.x; s1.y += val.y; s1.z += val.z; s1.w += val.w;
        s2.x += val.x * val.x; s2.y += val.y * val.y;
        s2.z += val.z * val.z; s2.w += val.w * val.w;
    }

    atomicAdd(&sstat[lane * 4 + 0], s1.x);
    atomicAdd(&sstat[lane * 4 + 1], s1.y);
    atomicAdd(&sstat[lane * 4 + 2], s1.z);
    atomicAdd(&sstat[lane * 4 + 3], s1.w);
    atomicAdd(&sstat[128 + lane * 4 + 0], s2.x);
    atomicAdd(&sstat[128 + lane * 4 + 1], s2.y);
    atomicAdd(&sstat[128 + lane * 4 + 2], s2.z);
    atomicAdd(&sstat[128 + lane * 4 + 3], s2.w);
    __syncthreads();
    atomicAdd(&g_stats[statsOff + tid], sstat[tid]);
}

// ---------------- CSR aggregate (C=40): fp16 gather, direct output --------------
__global__ void __launch_bounds__(256) k_agg40(const float* __restrict__ b3,
                                               float* __restrict__ out) {
    int tid = threadIdx.x;
    int lane = tid & 31;
    int gw = (blockIdx.x * blockDim.x + tid) >> 5;
    int nw = (gridDim.x * blockDim.x) >> 5;
    bool act = lane < 10;
    float4 b = make_float4(0.f, 0.f, 0.f, 0.f);
    if (act) b = *(const float4*)&b3[lane * 4];

    for (int n = gw; n < NN; n += nw) {
        int beg = g_off[n], end = g_off[n + 1];
        float4 acc = make_float4(0.f, 0.f, 0.f, 0.f);
        if (act) {
            uint2 u = *(const uint2*)&g_hs[(size_t)n * 40 + lane * 4];
            float2 f0 = __half22float2(*reinterpret_cast<__half2*>(&u.x));
            float2 f1 = __half22float2(*reinterpret_cast<__half2*>(&u.y));
            acc.x = f0.x; acc.y = f0.y; acc.z = f1.x; acc.w = f1.y;
        }
        for (int i = beg; i < end; i++) {
            int s = g_esrc[i];
            if (act) {
                uint2 u = *(const uint2*)&g_hs[(size_t)s * 40 + lane * 4];
                float2 f0 = __half22float2(*reinterpret_cast<__half2*>(&u.x));
                float2 f1 = __half22float2(*reinterpret_cast<__half2*>(&u.y));
                acc.x += f0.x; acc.y += f0.y; acc.z += f1.x; acc.w += f1.y;
            }
        }
        if (act) {
            float d = g_dinv[n];
            float4 o;
            o.x = fmaf(acc.x, d, b.x);
            o.y = fmaf(acc.y, d, b.y);
            o.z = fmaf(acc.z, d, b.z);
            o.w = fmaf(acc.w, d, b.w);
            *(float4*)&out[(size_t)n * 40 + lane * 4] = o;
        }
    }
}

// ---------------- finalize BN ----------------
__global__ void k_finalize(const float* __restrict__ gamma, const float* __restrict__ beta,
                           int statsOff, int scOff) {
    int c = threadIdx.x;            // 128 threads, 1 block
    float inv_n = 1.f / (float)NN;
    float mean = g_stats[statsOff + c] * inv_n;
    float var  = g_stats[statsOff + 128 + c] * inv_n - mean * mean;
    float inv  = rsqrtf(var + BN_EPS);
    float sc   = gamma[c] * inv;
    g_sc[scOff + c]       = sc;
    g_sc[scOff + 128 + c] = beta[c] - mean * sc;
}

// ---------------- launch: R10 schedule (CSR-build forked under GEMM1) ------------
extern "C" void kernel_launch(void* const* d_in, const int* in_sizes, int n_in,
                              void* d_out, int out_size) {
    const float* x    = (const float*)d_in[0];
    const int*   ei32 = (const int*)d_in[1];
    const float* W1 = (const float*)d_in[2];
    const float* b1 = (const float*)d_in[3];
    const float* g1 = (const float*)d_in[4];
    const float* t1 = (const float*)d_in[5];
    const float* W2 = (const float*)d_in[6];
    const float* b2 = (const float*)d_in[7];
    const float* g2 = (const float*)d_in[8];
    const float* t2 = (const float*)d_in[9];
    const float* W3 = (const float*)d_in[10];
    const float* b3 = (const float*)d_in[11];
    float* out = (float*)d_out;

    const int gemmBlocks = (NN + 127) / 128;     // 782
    const int aggBlocks  = 1184;
    const int edgeBlocks = (NE + 255) / 256;     // 6250

    static cudaStream_t s2 = nullptr;
    static cudaEvent_t evF = nullptr, evJ = nullptr;
    if (s2 == nullptr) {
        cudaStreamCreateWithFlags(&s2, cudaStreamNonBlocking);
        cudaEventCreateWithFlags(&evF, cudaEventDisableTiming);
        cudaEventCreateWithFlags(&evJ, cudaEventDisableTiming);
    }

    // preprocessing needed by GEMM1 epilogue (dinv) — on main stream
    k_init0  <<<(NN + 255) / 256, 256>>>(ei32);      // launch 1
    k_convert<<<edgeBlocks, 256>>>(ei32);            // launch 2
    k_dinv   <<<(NN + 255) / 256, 256>>>();          // launch 3

    // fork: CSR build on s2, GEMM1 on main
    cudaEventRecord(evF, 0);
    cudaStreamWaitEvent(s2, evF, 0);

    k_gemm128<false><<<gemmBlocks, 256>>>(x, W1, 0); // launch 4 (profiled slot)

    k_bsum <<<NSB, 256, 0, s2>>>();
    k_scanb<<<1, 1, 0, s2>>>();
    k_off  <<<NSB, 256, 0, s2>>>();
    k_place<<<edgeBlocks, 256, 0, s2>>>();

    // join before aggregate
    cudaEventRecord(evJ, s2);
    cudaStreamWaitEvent(0, evJ, 0);

    // layer 1 aggregate + BN
    k_agg128<<<aggBlocks, 256>>>(b1, 0);
    k_finalize<<<1, 128>>>(g1, t1, 0, 0);

    // layer 2 (BN+ReLU fused into A-load)
    k_gemm128<true><<<gemmBlocks, 256>>>(nullptr, W2, 0);
    k_agg128<<<aggBlocks, 256>>>(b2, 256);
    k_finalize<<<1, 128>>>(g2, t2, 256, 256);

    // layer 3 (output, 40 cols)
    k_gemm40<<<gemmBlocks, 256>>>(W3, 256);
    k_agg40<<<aggBlocks, 256>>>(b3, out);
}